// round 7
// baseline (speedup 1.0000x reference)
#include <cuda_runtime.h>

// NT-Xent loss. inp: (C=8, V=2, B=4096, D=512) fp32.
// Block per 4 b's (256 thr). 3-stage cp.async ring (32KB stages), ONE
// __syncthreads per tile. Mainloop per tile: per-lane 8x8 Gram tile
// (chunk = w*16 + (lane&15), lane bit4 = col half), 4-stage folded
// butterfly, STS folded G -> sPartAll[tile], odd sumsq -> sOddAll[tile].
// All LSE epilogues deferred: warp t handles tile t fully in-warp (R3 map:
// lane L owns G[L>>2][4*(L&3)+m]). Deterministic ticket finish.

static constexpr int      kB      = 4096;
static constexpr int      kIter   = 4;
static constexpr int      kGrid   = kB / kIter;        // 1024
static constexpr unsigned FULL    = 0xffffffffu;
static constexpr int      kTileF4 = 16 * 128;          // float4 per stage
static constexpr int      kRingB  = 3 * kTileF4 * 16;  // 96 KB
static constexpr int      kPartB  = kIter * 8 * 128 * 4;  // 16 KB
static constexpr int      kOddB   = kIter * 8 * 8 * 4;    // 1 KB
static constexpr int      kSmem   = kRingB + kPartB + kOddB;

__device__ float    g_partials[kGrid];
__device__ unsigned g_ticket;   // zero-init; reset by last CTA every launch

__device__ __forceinline__ float elem(const float4& v, int d) {
    return d == 0 ? v.x : d == 1 ? v.y : d == 2 ? v.z : v.w;
}

__global__ void __launch_bounds__(256, 2)
ntxent(const float* __restrict__ inp, float* __restrict__ out)
{
    extern __shared__ char dyn[];
    float4* Xs       = reinterpret_cast<float4*>(dyn);                  // [3][16][128]
    float*  sPartAll = reinterpret_cast<float*>(dyn + kRingB);          // [4][8][128]
    float*  sOddAll  = reinterpret_cast<float*>(dyn + kRingB + kPartB); // [4][8][8]
    __shared__ float    snorm[4][16];
    __shared__ float    sLossW[4];
    __shared__ float    sred[8];
    __shared__ unsigned sFlag;

    const int tid   = threadIdx.x;
    const int w     = tid >> 5;
    const int lane  = tid & 31;
    const int h     = lane >> 4;        // col half: k in [8h, 8h+8)
    const int L4    = lane & 15;
    const int chunk = w * 16 + L4;      // this lane's float4 d-chunk

    // cp.async assignment: thread t copies row = t>>4, chunks (t&15)+16m
    const int row = tid >> 4;
    const int c16 = tid & 15;
    const long long b0 = (long long)blockIdx.x * kIter;
    const char* gbase = (const char*)(inp + ((size_t)row * kB + b0) * 512) + c16 * 16;
    const unsigned sbase = (unsigned)__cvta_generic_to_shared(&Xs[row * 128 + c16]);

    auto issue = [&](int it) {
        const char*    g = gbase + (size_t)it * 2048;          // +512 floats per b
        const unsigned s = sbase + (it % 3) * (kTileF4 * 16);
        #pragma unroll
        for (int m = 0; m < 8; m++)
            asm volatile("cp.async.cg.shared.global [%0], [%1], 16;"
                         :: "r"(s + m * 256), "l"(g + m * 256));
        asm volatile("cp.async.commit_group;" ::: "memory");
    };

    issue(0);
    issue(1);

    #pragma unroll
    for (int it = 0; it < kIter; it++) {
        if (it < kIter - 1) asm volatile("cp.async.wait_group 1;" ::: "memory");
        else                asm volatile("cp.async.wait_group 0;" ::: "memory");
        __syncthreads();                       // single barrier per tile
        if (it + 2 < kIter) issue(it + 2);     // target buf consumed at it-1: safe

        const float4* X = Xs + (it % 3) * kTileF4;

        // ---- per-lane 8x8 Gram tile + odd-row sumsq ----
        float4 A[8];
        #pragma unroll
        for (int i = 0; i < 8; i++) A[i] = X[(2 * i) * 128 + chunk];

        float a[64];
        #pragma unroll
        for (int q = 0; q < 64; q++) a[q] = 0.f;
        float ssv[4] = {0.f, 0.f, 0.f, 0.f};

        #pragma unroll
        for (int jg = 0; jg < 2; jg++) {
            float4 Cv[4];
            #pragma unroll
            for (int jj = 0; jj < 4; jj++)
                Cv[jj] = X[(8 * h + jg * 4 + jj) * 128 + chunk];
            #pragma unroll
            for (int o = 0; o < 2; o++) {      // odd rows j = jg*4 + {1,3}
                const float4 x = Cv[2 * o + 1];
                float s = ssv[jg * 2 + o];
                s = fmaf(x.x, x.x, fmaf(x.y, x.y, fmaf(x.z, x.z, fmaf(x.w, x.w, s))));
                ssv[jg * 2 + o] = s;
            }
            #pragma unroll
            for (int d = 0; d < 4; d++)
                #pragma unroll
                for (int i = 0; i < 8; i++) {
                    const float av = elem(A[i], d);
                    #pragma unroll
                    for (int jj = 0; jj < 4; jj++)
                        a[i * 8 + jg * 4 + jj] =
                            fmaf(av, elem(Cv[jj], d), a[i * 8 + jg * 4 + jj]);
                }
        }

        // ---- folded butterfly over 16 chunk-lanes (bits 3..0) ----
        #pragma unroll
        for (int s = 0; s < 4; s++) {
            const int  off = 8 >> s;
            const int  n   = 32 >> s;
            const bool hi  = (lane & off) != 0;
            #pragma unroll
            for (int m = 0; m < n; m++) {
                const float mine = hi ? a[m + n] : a[m];
                const float send = hi ? a[m]     : a[m + n];
                a[m] = mine + __shfl_xor_sync(FULL, send, off);
            }
        }
        // lane owns flat64 = 4*L4 + m: i = L4>>1, k = (L4&1)*4 + 8h + m
        {
            const int i  = L4 >> 1;
            const int kb = (L4 & 1) * 4 + 8 * h;
            *reinterpret_cast<float4*>(
                &sPartAll[(it * 8 + w) * 128 + i * 16 + kb]) =
                make_float4(a[0], a[1], a[2], a[3]);
        }
        #pragma unroll
        for (int off = 8; off > 0; off >>= 1)
            #pragma unroll
            for (int q = 0; q < 4; q++)
                ssv[q] += __shfl_xor_sync(FULL, ssv[q], off);
        if (L4 == 0) {
            #pragma unroll
            for (int q = 0; q < 4; q++)
                sOddAll[(it * 8 + w) * 8 + q + 4 * h] = ssv[q];  // row 2*(q+4h)+1
        }
    }
    __syncthreads();

    // ---- deferred epilogues: warp t handles tile t, fully in-warp ----
    if (w < 4) {
        const int i  = lane >> 2;
        const int kb = 4 * (lane & 3);
        float4 acc = make_float4(0.f, 0.f, 0.f, 0.f);
        #pragma unroll
        for (int ww = 0; ww < 8; ww++) {
            const float4 p = *reinterpret_cast<const float4*>(
                &sPartAll[(w * 8 + ww) * 128 + i * 16 + kb]);
            acc.x += p.x; acc.y += p.y; acc.z += p.z; acc.w += p.w;
        }
        float a4[4] = {acc.x, acc.y, acc.z, acc.w};

        if (lane < 8) {
            float so = 0.f;
            #pragma unroll
            for (int ww = 0; ww < 8; ww++) so += sOddAll[(w * 8 + ww) * 8 + lane];
            snorm[w][2 * lane + 1] = so;
        }
        #pragma unroll
        for (int m = 0; m < 4; m++)                 // even norms = Gram diag
            if (kb + m == 2 * i) snorm[w][2 * i] = a4[m];
        __syncwarp();

        const float inva = 1.0f / fmaxf(sqrtf(snorm[w][2 * i]), 1e-12f);
        float sim[4];
        bool  val[4];
        float mx = -3.0e38f;
        #pragma unroll
        for (int m = 0; m < 4; m++) {
            const int   k    = kb + m;
            const float invk = 1.0f / fmaxf(sqrtf(snorm[w][k]), 1e-12f);
            sim[m] = a4[m] * inva * invk * 10.0f;
            val[m] = ((k >> 1) != i) || (k == 2 * i + 1);
            if (val[m]) mx = fmaxf(mx, sim[m]);
        }
        mx = fmaxf(mx, __shfl_xor_sync(FULL, mx, 1));
        mx = fmaxf(mx, __shfl_xor_sync(FULL, mx, 2));
        float sum = 0.f;
        #pragma unroll
        for (int m = 0; m < 4; m++)
            if (val[m]) sum += __expf(sim[m] - mx);
        sum += __shfl_xor_sync(FULL, sum, 1);
        sum += __shfl_xor_sync(FULL, sum, 2);

        float contrib = 0.f;
        #pragma unroll
        for (int m = 0; m < 4; m++)
            if (kb + m == 2 * i + 1)                // this sim is the positive
                contrib = (mx + __logf(sum)) - sim[m];
        #pragma unroll
        for (int off = 16; off > 0; off >>= 1)
            contrib += __shfl_xor_sync(FULL, contrib, off);
        if (lane == 0) sLossW[w] = contrib;
    }
    __syncthreads();

    // ---- deterministic fused finish ----
    if (tid == 0) {
        g_partials[blockIdx.x] = sLossW[0] + sLossW[1] + sLossW[2] + sLossW[3];
        __threadfence();
        const unsigned tk = atomicAdd(&g_ticket, 1u);
        sFlag = (tk == kGrid - 1) ? 1u : 0u;
    }
    __syncthreads();
    if (sFlag) {
        float s = 0.f;
        #pragma unroll
        for (int m = 0; m < kGrid / 256; m++)
            s += __ldcg(&g_partials[tid + m * 256]);   // fixed order
        #pragma unroll
        for (int off = 16; off > 0; off >>= 1)
            s += __shfl_xor_sync(FULL, s, off);
        if (lane == 0) sred[w] = s;
        __syncthreads();
        if (tid == 0) {
            float tot = 0.f;
            #pragma unroll
            for (int i = 0; i < 8; i++) tot += sred[i];
            out[0] = tot * (1.0f / (8.0f * 4096.0f));
            g_ticket = 0u;   // reset for next graph replay
        }
    }
}

extern "C" void kernel_launch(void* const* d_in, const int* in_sizes, int n_in,
                              void* d_out, int out_size) {
    (void)in_sizes; (void)n_in; (void)out_size;
    const float* inp = (const float*)d_in[0];
    cudaFuncSetAttribute(ntxent, cudaFuncAttributeMaxDynamicSharedMemorySize, kSmem);
    ntxent<<<kGrid, 256, kSmem>>>(inp, (float*)d_out);
}

// round 10
// speedup vs baseline: 1.3323x; 1.3323x over previous
#include <cuda_runtime.h>

// NT-Xent loss. inp: (C=8, V=2, B=4096, D=512) fp32.
// Block per 4 b's (256 thr). 2-stage cp.async ring (32KB stages), ONE
// __syncthreads per tile, prefetch distance 1 (issue right after barrier).
// Mainloop per tile: per-lane 8x8 Gram tile (chunk = w*16 + (lane&15),
// lane bit4 = col half), 4-stage folded butterfly, STS folded G ->
// sPartAll[tile], odd sumsq -> sOddAll[tile]. All LSE epilogues deferred:
// warp t handles tile t fully in-warp. Deterministic ticket finish.
// Dynamic smem 81KB -> 2 CTAs/SM (the R7 regression was 113KB -> 1 CTA/SM).

static constexpr int      kB      = 4096;
static constexpr int      kIter   = 4;
static constexpr int      kGrid   = kB / kIter;        // 1024
static constexpr unsigned FULL    = 0xffffffffu;
static constexpr int      kTileF4 = 16 * 128;          // float4 per stage
static constexpr int      kRingB  = 2 * kTileF4 * 16;  // 64 KB
static constexpr int      kPartB  = kIter * 8 * 128 * 4;  // 16 KB
static constexpr int      kOddB   = kIter * 8 * 8 * 4;    // 1 KB
static constexpr int      kSmem   = kRingB + kPartB + kOddB;  // 81 KB

__device__ float    g_partials[kGrid];
__device__ unsigned g_ticket;   // zero-init; reset by last CTA every launch

__device__ __forceinline__ float elem(const float4& v, int d) {
    return d == 0 ? v.x : d == 1 ? v.y : d == 2 ? v.z : v.w;
}

__global__ void __launch_bounds__(256, 2)
ntxent(const float* __restrict__ inp, float* __restrict__ out)
{
    extern __shared__ char dyn[];
    float4* Xs       = reinterpret_cast<float4*>(dyn);                  // [2][16][128]
    float*  sPartAll = reinterpret_cast<float*>(dyn + kRingB);          // [4][8][128]
    float*  sOddAll  = reinterpret_cast<float*>(dyn + kRingB + kPartB); // [4][8][8]
    __shared__ float    snorm[4][16];
    __shared__ float    sLossW[4];
    __shared__ float    sred[8];
    __shared__ unsigned sFlag;

    const int tid   = threadIdx.x;
    const int w     = tid >> 5;
    const int lane  = tid & 31;
    const int h     = lane >> 4;        // col half: k in [8h, 8h+8)
    const int L4    = lane & 15;
    const int chunk = w * 16 + L4;      // this lane's float4 d-chunk

    // cp.async assignment: thread t copies row = t>>4, chunks (t&15)+16m
    const int row = tid >> 4;
    const int c16 = tid & 15;
    const long long b0 = (long long)blockIdx.x * kIter;
    const char* gbase = (const char*)(inp + ((size_t)row * kB + b0) * 512) + c16 * 16;
    const unsigned sbase = (unsigned)__cvta_generic_to_shared(&Xs[row * 128 + c16]);

    auto issue = [&](int it) {
        const char*    g = gbase + (size_t)it * 2048;          // +512 floats per b
        const unsigned s = sbase + (it & 1) * (kTileF4 * 16);
        #pragma unroll
        for (int m = 0; m < 8; m++)
            asm volatile("cp.async.cg.shared.global [%0], [%1], 16;"
                         :: "r"(s + m * 256), "l"(g + m * 256));
        asm volatile("cp.async.commit_group;" ::: "memory");
    };

    issue(0);

    #pragma unroll
    for (int it = 0; it < kIter; it++) {
        asm volatile("cp.async.wait_group 0;" ::: "memory");
        __syncthreads();                      // single barrier per tile
        if (it + 1 < kIter) issue(it + 1);    // target buf consumed at it-1: safe

        const float4* X = Xs + (it & 1) * kTileF4;

        // ---- per-lane 8x8 Gram tile + odd-row sumsq ----
        float4 A[8];
        #pragma unroll
        for (int i = 0; i < 8; i++) A[i] = X[(2 * i) * 128 + chunk];

        float a[64];
        #pragma unroll
        for (int q = 0; q < 64; q++) a[q] = 0.f;
        float ssv[4] = {0.f, 0.f, 0.f, 0.f};

        #pragma unroll
        for (int jg = 0; jg < 2; jg++) {
            float4 Cv[4];
            #pragma unroll
            for (int jj = 0; jj < 4; jj++)
                Cv[jj] = X[(8 * h + jg * 4 + jj) * 128 + chunk];
            #pragma unroll
            for (int o = 0; o < 2; o++) {     // odd rows j = jg*4 + {1,3}
                const float4 x = Cv[2 * o + 1];
                float s = ssv[jg * 2 + o];
                s = fmaf(x.x, x.x, fmaf(x.y, x.y, fmaf(x.z, x.z, fmaf(x.w, x.w, s))));
                ssv[jg * 2 + o] = s;
            }
            #pragma unroll
            for (int d = 0; d < 4; d++)
                #pragma unroll
                for (int i = 0; i < 8; i++) {
                    const float av = elem(A[i], d);
                    #pragma unroll
                    for (int jj = 0; jj < 4; jj++)
                        a[i * 8 + jg * 4 + jj] =
                            fmaf(av, elem(Cv[jj], d), a[i * 8 + jg * 4 + jj]);
                }
        }

        // ---- folded butterfly over 16 chunk-lanes (bits 3..0) ----
        #pragma unroll
        for (int s = 0; s < 4; s++) {
            const int  off = 8 >> s;
            const int  n   = 32 >> s;
            const bool hi  = (lane & off) != 0;
            #pragma unroll
            for (int m = 0; m < n; m++) {
                const float mine = hi ? a[m + n] : a[m];
                const float send = hi ? a[m]     : a[m + n];
                a[m] = mine + __shfl_xor_sync(FULL, send, off);
            }
        }
        // lane owns flat64 = 4*L4 + m: i = L4>>1, k = (L4&1)*4 + 8h + m
        {
            const int i  = L4 >> 1;
            const int kb = (L4 & 1) * 4 + 8 * h;
            *reinterpret_cast<float4*>(
                &sPartAll[(it * 8 + w) * 128 + i * 16 + kb]) =
                make_float4(a[0], a[1], a[2], a[3]);
        }
        #pragma unroll
        for (int off = 8; off > 0; off >>= 1)
            #pragma unroll
            for (int q = 0; q < 4; q++)
                ssv[q] += __shfl_xor_sync(FULL, ssv[q], off);
        if (L4 == 0) {
            #pragma unroll
            for (int q = 0; q < 4; q++)
                sOddAll[(it * 8 + w) * 8 + q + 4 * h] = ssv[q];  // row 2*(q+4h)+1
        }
    }
    __syncthreads();

    // ---- deferred epilogues: warp t handles tile t, fully in-warp ----
    if (w < 4) {
        const int i  = lane >> 2;
        const int kb = 4 * (lane & 3);
        float4 acc = make_float4(0.f, 0.f, 0.f, 0.f);
        #pragma unroll
        for (int ww = 0; ww < 8; ww++) {
            const float4 p = *reinterpret_cast<const float4*>(
                &sPartAll[(w * 8 + ww) * 128 + i * 16 + kb]);
            acc.x += p.x; acc.y += p.y; acc.z += p.z; acc.w += p.w;
        }
        float a4[4] = {acc.x, acc.y, acc.z, acc.w};

        if (lane < 8) {
            float so = 0.f;
            #pragma unroll
            for (int ww = 0; ww < 8; ww++) so += sOddAll[(w * 8 + ww) * 8 + lane];
            snorm[w][2 * lane + 1] = so;
        }
        #pragma unroll
        for (int m = 0; m < 4; m++)                 // even norms = Gram diag
            if (kb + m == 2 * i) snorm[w][2 * i] = a4[m];
        __syncwarp();

        const float inva = 1.0f / fmaxf(sqrtf(snorm[w][2 * i]), 1e-12f);
        float sim[4];
        bool  val[4];
        float mx = -3.0e38f;
        #pragma unroll
        for (int m = 0; m < 4; m++) {
            const int   k    = kb + m;
            const float invk = 1.0f / fmaxf(sqrtf(snorm[w][k]), 1e-12f);
            sim[m] = a4[m] * inva * invk * 10.0f;
            val[m] = ((k >> 1) != i) || (k == 2 * i + 1);
            if (val[m]) mx = fmaxf(mx, sim[m]);
        }
        mx = fmaxf(mx, __shfl_xor_sync(FULL, mx, 1));
        mx = fmaxf(mx, __shfl_xor_sync(FULL, mx, 2));
        float sum = 0.f;
        #pragma unroll
        for (int m = 0; m < 4; m++)
            if (val[m]) sum += __expf(sim[m] - mx);
        sum += __shfl_xor_sync(FULL, sum, 1);
        sum += __shfl_xor_sync(FULL, sum, 2);

        float contrib = 0.f;
        #pragma unroll
        for (int m = 0; m < 4; m++)
            if (kb + m == 2 * i + 1)                // this sim is the positive
                contrib = (mx + __logf(sum)) - sim[m];
        #pragma unroll
        for (int off = 16; off > 0; off >>= 1)
            contrib += __shfl_xor_sync(FULL, contrib, off);
        if (lane == 0) sLossW[w] = contrib;
    }
    __syncthreads();

    // ---- deterministic fused finish ----
    if (tid == 0) {
        g_partials[blockIdx.x] = sLossW[0] + sLossW[1] + sLossW[2] + sLossW[3];
        __threadfence();
        const unsigned tk = atomicAdd(&g_ticket, 1u);
        sFlag = (tk == kGrid - 1) ? 1u : 0u;
    }
    __syncthreads();
    if (sFlag) {
        float s = 0.f;
        #pragma unroll
        for (int m = 0; m < kGrid / 256; m++)
            s += __ldcg(&g_partials[tid + m * 256]);   // fixed order
        #pragma unroll
        for (int off = 16; off > 0; off >>= 1)
            s += __shfl_xor_sync(FULL, s, off);
        if (lane == 0) sred[w] = s;
        __syncthreads();
        if (tid == 0) {
            float tot = 0.f;
            #pragma unroll
            for (int i = 0; i < 8; i++) tot += sred[i];
            out[0] = tot * (1.0f / (8.0f * 4096.0f));
            g_ticket = 0u;   // reset for next graph replay
        }
    }
}

extern "C" void kernel_launch(void* const* d_in, const int* in_sizes, int n_in,
                              void* d_out, int out_size) {
    (void)in_sizes; (void)n_in; (void)out_size;
    const float* inp = (const float*)d_in[0];
    cudaFuncSetAttribute(ntxent, cudaFuncAttributeMaxDynamicSharedMemorySize, kSmem);
    ntxent<<<kGrid, 256, kSmem>>>(inp, (float*)d_out);
}